// round 15
// baseline (speedup 1.0000x reference)
#include <cuda_runtime.h>
#include <cuda_bf16.h>
#include <stdint.h>
#include <math.h>
#include <float.h>

#define DD   64
#define TT   4096
#define NN   20000
#define MM   24096     // TT + NN
#define EE   100000
#define RR   50
#define TOKN 768

// ---------------- scratch (device globals; no allocation allowed) ----------------
__device__ __align__(16) float g_x[MM*DD];
__device__ __align__(16) float g_h[MM*DD];
__device__ __align__(16) float g_fx[MM*DD];
__device__ __align__(16) float g_aggr[MM*DD];
__device__ __align__(16) float g_u1[RR*DD];
__device__ __align__(16) float g_u2[RR*DD];
__device__ __align__(16) __nv_bfloat16 g_bhi[TOKN*DD];    // w_lin2^T hi [768][64]
__device__ __align__(16) __nv_bfloat16 g_blo[TOKN*DD];    // w_lin2^T lo
__device__ __align__(16) __nv_bfloat16 g_b1hi[DD*TOKN];   // w_lin1^T hi [64][768]
__device__ __align__(16) __nv_bfloat16 g_b1lo[DD*TOKN];
__device__ __align__(16) __nv_bfloat16 g_r1hi[DD*DD];     // root1^T hi [64][64]
__device__ __align__(16) __nv_bfloat16 g_r1lo[DD*DD];
__device__ __align__(16) __nv_bfloat16 g_r2hi[DD*DD];     // root2^T hi
__device__ __align__(16) __nv_bfloat16 g_r2lo[DD*DD];
__device__ int   g_rel[EE];
__device__ float g_mask[EE];
__device__ float g_p[MM];
__device__ float g_sum1, g_sum2;
__device__ float g_kge;
__device__ float g_nt;

// ---------------- helpers ----------------
__device__ __forceinline__ uint32_t pack_bf2(float a, float b) {
    __nv_bfloat162 t = __floats2bfloat162_rn(a, b);
    return *(uint32_t*)&t;
}

__device__ __forceinline__ void mma_bf16(float* c, const uint32_t* a,
                                         uint32_t b0, uint32_t b1) {
    asm volatile(
        "mma.sync.aligned.m16n8k16.row.col.f32.bf16.bf16.f32 "
        "{%0,%1,%2,%3}, {%4,%5,%6,%7}, {%8,%9}, {%0,%1,%2,%3};"
        : "+f"(c[0]), "+f"(c[1]), "+f"(c[2]), "+f"(c[3])
        : "r"(a[0]), "r"(a[1]), "r"(a[2]), "r"(a[3]), "r"(b0), "r"(b1));
}

#define BSTR 72   // smem B row stride in bf16

// ================ generic N=64 HMMA split-bf16 GEMM =================================
// C[M,64] = A[M,Kdim] @ B[Kdim,64] (+bias)(+addsrc*inv)(relu)(zero addsrc)(atomic)
template<int RELU, int HASADD, int ZEROADD, int ATOMIC, int SCALEADD>
__global__ void __launch_bounds__(256, 2)
k_mma_n64(const float* __restrict__ A,
          const __nv_bfloat16* __restrict__ Bhi, const __nv_bfloat16* __restrict__ Blo,
          const float* __restrict__ bias, float* __restrict__ addsrc,
          const float* __restrict__ scale,
          float* __restrict__ C, int Mrows, int Kdim, int kPerZ)
{
    __shared__ __nv_bfloat16 smBhi[64 * BSTR];
    __shared__ __nv_bfloat16 smBlo[64 * BSTR];
    int tid  = threadIdx.x;
    int wid  = tid >> 5;
    int lane = tid & 31;
    int g    = lane >> 2;
    int tg   = lane & 3;
    int row0 = blockIdx.y * 128;
    int rbase = row0 + wid * 16;

    float acc[8][4];
    #pragma unroll
    for (int nt = 0; nt < 8; nt++)
        #pragma unroll
        for (int j = 0; j < 4; j++) acc[nt][j] = 0.f;

    int kb = blockIdx.z * kPerZ;
    for (int kc = kb; kc < kb + kPerZ; kc += 64) {
        for (int i = tid; i < 64 * 16; i += 256) {
            int n = i >> 4, q = i & 15;
            uint2 h = *(const uint2*)&Bhi[(long)n * Kdim + kc + q * 4];
            uint2 l = *(const uint2*)&Blo[(long)n * Kdim + kc + q * 4];
            *(uint2*)&smBhi[n * BSTR + q * 4] = h;
            *(uint2*)&smBlo[n * BSTR + q * 4] = l;
        }
        __syncthreads();

        #pragma unroll
        for (int ks = 0; ks < 4; ks++) {
            int k0 = ks * 16;
            uint32_t ahi[4], alo[4];
            #pragma unroll
            for (int i = 0; i < 4; i++) {
                int r = rbase + g + (i & 1) * 8;
                int k = kc + k0 + tg * 2 + (i >> 1) * 8;
                float2 v = make_float2(0.f, 0.f);
                if (r < Mrows) v = *(const float2*)&A[(long)r * Kdim + k];
                float hx = __bfloat162float(__float2bfloat16(v.x));
                float hy = __bfloat162float(__float2bfloat16(v.y));
                ahi[i] = pack_bf2(v.x, v.y);
                alo[i] = pack_bf2(v.x - hx, v.y - hy);
            }
            #pragma unroll
            for (int nt = 0; nt < 8; nt++) {
                int n = nt * 8 + g;
                uint32_t b0h = *(const uint32_t*)&smBhi[n * BSTR + k0 + tg * 2];
                uint32_t b1h = *(const uint32_t*)&smBhi[n * BSTR + k0 + tg * 2 + 8];
                uint32_t b0l = *(const uint32_t*)&smBlo[n * BSTR + k0 + tg * 2];
                uint32_t b1l = *(const uint32_t*)&smBlo[n * BSTR + k0 + tg * 2 + 8];
                mma_bf16(acc[nt], ahi, b0h, b1h);
                mma_bf16(acc[nt], ahi, b0l, b1l);
                mma_bf16(acc[nt], alo, b0h, b1h);
            }
        }
        __syncthreads();
    }

    float inv = 1.f;
    if (SCALEADD) inv = 1.f / *scale;
    bool addbias = !ATOMIC || (blockIdx.z == 0);
    #pragma unroll
    for (int nt = 0; nt < 8; nt++) {
        int c = nt * 8 + tg * 2;
        float2 bv = *(const float2*)&bias[c];
        #pragma unroll
        for (int half = 0; half < 2; half++) {
            int r = rbase + g + half * 8;
            if (r >= Mrows) continue;
            float vx = acc[nt][half*2];
            float vy = acc[nt][half*2 + 1];
            if (addbias) { vx += bv.x; vy += bv.y; }
            if (HASADD) {
                float2 ad = *(float2*)&addsrc[(long)r * 64 + c];
                vx += ad.x * inv; vy += ad.y * inv;
                if (ZEROADD)
                    *(float2*)&addsrc[(long)r * 64 + c] = make_float2(0.f, 0.f);
            }
            if (RELU) { vx = fmaxf(vx, 0.f); vy = fmaxf(vy, 0.f); }
            if (ATOMIC) {
                atomicAdd(&C[(long)r * 64 + c],     vx);
                atomicAdd(&C[(long)r * 64 + c + 1], vy);
            } else {
                *(float2*)&C[(long)r * 64 + c] = make_float2(vx, vy);
            }
        }
    }
}

// ======== final HMMA split-bf16 GEMM: out[M,768] = fx[M,64] @ w_lin2 + bias ========
__global__ void k_wsplit(const float* __restrict__ w_lin2)
{
    int idx = blockIdx.x * blockDim.x + threadIdx.x;
    if (idx >= TOKN * DD) return;
    int n = idx >> 6, k = idx & 63;
    float v = w_lin2[(long)k * TOKN + n];
    __nv_bfloat16 hi = __float2bfloat16(v);
    g_bhi[idx] = hi;
    g_blo[idx] = __float2bfloat16(v - __bfloat162float(hi));
}

// split+transpose w_lin1 [768,64] -> [64][768], root1/root2 [64,64] -> [64][64]
__global__ void k_bsplit(const float* __restrict__ w_lin1,
                         const float* __restrict__ root1,
                         const float* __restrict__ root2)
{
    int idx = blockIdx.x * blockDim.x + threadIdx.x;
    if (idx < DD * TOKN) {
        int n = idx / TOKN, k = idx % TOKN;
        float v = w_lin1[(long)k * DD + n];
        __nv_bfloat16 hi = __float2bfloat16(v);
        g_b1hi[idx] = hi;
        g_b1lo[idx] = __float2bfloat16(v - __bfloat162float(hi));
    } else if (idx < DD * TOKN + DD * DD) {
        int j = idx - DD * TOKN;
        int n = j >> 6, k = j & 63;
        float v = root1[k * DD + n];
        __nv_bfloat16 hi = __float2bfloat16(v);
        g_r1hi[j] = hi;
        g_r1lo[j] = __float2bfloat16(v - __bfloat162float(hi));
    } else if (idx < DD * TOKN + 2 * DD * DD) {
        int j = idx - DD * TOKN - DD * DD;
        int n = j >> 6, k = j & 63;
        float v = root2[k * DD + n];
        __nv_bfloat16 hi = __float2bfloat16(v);
        g_r2hi[j] = hi;
        g_r2lo[j] = __float2bfloat16(v - __bfloat162float(hi));
    }
}

__global__ void __launch_bounds__(256, 2)
k_gemm_mma(const float* __restrict__ A, const float* __restrict__ bias,
           float* __restrict__ out)
{
    __shared__ __nv_bfloat16 smBhi[64 * BSTR];
    __shared__ __nv_bfloat16 smBlo[64 * BSTR];
    int tid  = threadIdx.x;
    int wid  = tid >> 5;
    int lane = tid & 31;
    int g    = lane >> 2;
    int tg   = lane & 3;
    int col0 = blockIdx.x * 64;
    int row0 = blockIdx.y * 128;

    for (int i = tid; i < 64 * 16; i += 256) {
        int n = i >> 4, q = i & 15;
        uint2 h = *(const uint2*)&g_bhi[(long)(col0 + n) * DD + q * 4];
        uint2 l = *(const uint2*)&g_blo[(long)(col0 + n) * DD + q * 4];
        *(uint2*)&smBhi[n * BSTR + q * 4] = h;
        *(uint2*)&smBlo[n * BSTR + q * 4] = l;
    }
    __syncthreads();

    float acc[8][4];
    #pragma unroll
    for (int nt = 0; nt < 8; nt++)
        #pragma unroll
        for (int j = 0; j < 4; j++) acc[nt][j] = 0.f;

    int rbase = row0 + wid * 16;

    #pragma unroll
    for (int ks = 0; ks < 4; ks++) {
        int k0 = ks * 16;
        uint32_t ahi[4], alo[4];
        #pragma unroll
        for (int i = 0; i < 4; i++) {
            int r = rbase + g + (i & 1) * 8;
            int k = k0 + tg * 2 + (i >> 1) * 8;
            float2 v = make_float2(0.f, 0.f);
            if (r < MM) v = *(const float2*)&A[(long)r * DD + k];
            float hx = __bfloat162float(__float2bfloat16(v.x));
            float hy = __bfloat162float(__float2bfloat16(v.y));
            ahi[i] = pack_bf2(v.x, v.y);
            alo[i] = pack_bf2(v.x - hx, v.y - hy);
        }
        #pragma unroll
        for (int nt = 0; nt < 8; nt++) {
            int n = nt * 8 + g;
            uint32_t b0h = *(const uint32_t*)&smBhi[n * BSTR + k0 + tg * 2];
            uint32_t b1h = *(const uint32_t*)&smBhi[n * BSTR + k0 + tg * 2 + 8];
            uint32_t b0l = *(const uint32_t*)&smBlo[n * BSTR + k0 + tg * 2];
            uint32_t b1l = *(const uint32_t*)&smBlo[n * BSTR + k0 + tg * 2 + 8];
            mma_bf16(acc[nt], ahi, b0h, b1h);
            mma_bf16(acc[nt], ahi, b0l, b1l);
            mma_bf16(acc[nt], alo, b0h, b1h);
        }
    }

    #pragma unroll
    for (int nt = 0; nt < 8; nt++) {
        int c = col0 + nt * 8 + tg * 2;
        float2 bv = *(const float2*)&bias[c];
        int r0w = rbase + g;
        if (r0w < MM)
            *(float2*)&out[(long)r0w * TOKN + c] =
                make_float2(acc[nt][0] + bv.x, acc[nt][1] + bv.y);
        int r1w = rbase + g + 8;
        if (r1w < MM)
            *(float2*)&out[(long)r1w * TOKN + c] =
                make_float2(acc[nt][2] + bv.x, acc[nt][3] + bv.y);
    }
}

// ---------------- init: zero aggr, gather kg nodes, reset scalars ----------------
__global__ void k_init(const int* __restrict__ node_ids, const float* __restrict__ kg_emb)
{
    int idx = blockIdx.x * blockDim.x + threadIdx.x;   // float4 units
    float4 z = make_float4(0.f, 0.f, 0.f, 0.f);
    if (idx < MM*16) ((float4*)g_aggr)[idx] = z;
    if (idx < NN*16) {
        int n = idx >> 4, q = idx & 15;
        ((float4*)g_x)[(long)(TT + n)*16 + q] =
            ((const float4*)kg_emb)[(long)node_ids[n]*16 + q];
    }
    if (idx == 0) { g_kge = 0.f; g_nt = 0.f; g_sum1 = 0.f; g_sum2 = 0.f; }
}

// ---------------- zero token region of x ----------------
__global__ void k_zerotok()
{
    int idx = blockIdx.x * blockDim.x + threadIdx.x;
    if (idx < TT*16) ((float4*)g_x)[idx] = make_float4(0.f, 0.f, 0.f, 0.f);
}

// ---------------- relation id + mask (float4 smem staging) ----------------
#define EPB 128
#define EB  ((EE + EPB - 1) / EPB)
__global__ void k_relmask(const float* __restrict__ ea)
{
    __shared__ float smr[EPB * RR];
    int e0 = blockIdx.x * EPB;
    int cnt = min(EPB, EE - e0);
    int total4 = (cnt * RR) >> 2;
    const float4* base4 = (const float4*)(ea + (long)e0 * RR);
    float4* sm4 = (float4*)smr;
    for (int i = threadIdx.x; i < total4; i += 256) sm4[i] = base4[i];
    __syncthreads();
    int el = threadIdx.x;
    if (el < cnt) {
        const float* row = smr + el * RR;
        float acc = 0.f;
        #pragma unroll
        for (int r = 1; r < RR; r++) acc += row[r] * (float)r;
        g_rel[e0 + el] = (int)(acc + 0.5f);
        g_mask[e0 + el] = (row[47] + row[48] + row[49] == 0.f) ? 1.f : 0.f;
    }
}

// ---- fused u-tables ----
__global__ void __launch_bounds__(256)
k_ufused(const float* __restrict__ rel_emb, const float* __restrict__ w_e2,
         const float* __restrict__ b_e2,
         const float* __restrict__ att1_w, const float* __restrict__ att2_w)
{
    __shared__ float ws[64*64];
    __shared__ float re[RR*64];
    int tid = threadIdx.x;
    int d = blockIdx.x;

    for (int i = tid; i < 64*64; i += 256) {
        int k = i >> 6, o = i & 63;
        ws[i] = w_e2[(long)k*4096 + d*64 + o];
    }
    for (int i = tid; i < RR*64; i += 256) re[i] = rel_emb[i];
    __syncthreads();

    int wid = tid >> 5, lane = tid & 31;
    float b1 = b_e2[d*64 + lane];
    float b2 = b_e2[d*64 + lane + 32];
    float w1a = att1_w[64 + lane], w1b = att1_w[64 + lane + 32];
    float w2a = att2_w[64 + lane], w2b = att2_w[64 + lane + 32];

    for (int rel = wid; rel < RR; rel += 8) {
        float acc1 = b1, acc2 = b2;
        const float* rr = re + rel*64;
        #pragma unroll
        for (int k = 0; k < 64; k++) {
            float rv = rr[k];
            acc1 += rv * ws[k*64 + lane];
            acc2 += rv * ws[k*64 + lane + 32];
        }
        acc1 = fmaxf(acc1, 0.f); acc2 = fmaxf(acc2, 0.f);
        float a1 = acc1*w1a + acc2*w1b;
        float a2 = acc1*w2a + acc2*w2b;
        #pragma unroll
        for (int s = 16; s; s >>= 1) {
            a1 += __shfl_down_sync(0xffffffff, a1, s);
            a2 += __shfl_down_sync(0xffffffff, a2, s);
        }
        if (lane == 0) { g_u1[rel*64 + d] = a1; g_u2[rel*64 + d] = a2; }
    }
}

// ---------------- per-node dst-side attention term ----------------
__global__ void k_p(const float* __restrict__ x, const float* __restrict__ att_w,
                    const float* __restrict__ att_b)
{
    int n = blockIdx.x * blockDim.x + threadIdx.x;
    if (n >= MM) return;
    float acc = att_b[0];
    const float4* xr = (const float4*)(x + (long)n * DD);
    const float4* wr = (const float4*)att_w;
    #pragma unroll
    for (int k = 0; k < 16; k++) {
        float4 a = xr[k], w = wr[k];
        acc += a.x*w.x + a.y*w.y + a.z*w.z + a.w*w.w;
    }
    g_p[n] = acc;
}

// ======= fused edge phase: logit -> exp -> UNNORMALIZED scatter + sum accumulation ====
// aggr[dst] += exp(logit) * x[src]; sum accumulated; normalization folded into GEMM.
__global__ void __launch_bounds__(256)
k_edgefused(const float* __restrict__ x, const float* __restrict__ u,
            const int* __restrict__ src, const int* __restrict__ dst,
            float* __restrict__ psum)
{
    __shared__ float smr[256];
    int e = blockIdx.x * 256 + threadIdx.x;
    float v = 0.f;
    if (e < EE) {
        int d = dst[e];
        float acc = g_p[d];
        float4 xr[16];
        const float4* xp = (const float4*)(x + (long)src[e] * DD);
        const float4* ur = (const float4*)(u + g_rel[e] * DD);
        #pragma unroll
        for (int k = 0; k < 16; k++) {
            xr[k] = xp[k];
            float4 w = ur[k];
            acc += xr[k].x*w.x + xr[k].y*w.y + xr[k].z*w.z + xr[k].w*w.w;
        }
        v = __expf(acc);
        float* ap = &g_aggr[(long)d * DD];
        #pragma unroll
        for (int k = 0; k < 16; k++) {
            atomicAdd(ap + k*4 + 0, xr[k].x * v);
            atomicAdd(ap + k*4 + 1, xr[k].y * v);
            atomicAdd(ap + k*4 + 2, xr[k].z * v);
            atomicAdd(ap + k*4 + 3, xr[k].w * v);
        }
    }
    smr[threadIdx.x] = v; __syncthreads();
    for (int s = 128; s > 0; s >>= 1) {
        if (threadIdx.x < s) smr[threadIdx.x] += smr[threadIdx.x + s];
        __syncthreads();
    }
    if (threadIdx.x == 0) atomicAdd(psum, smr[0]);
}

// ---------------- fused losses ----------------
#define KB 512
__global__ void k_loss(const int* __restrict__ src, const int* __restrict__ dst,
                       const float* __restrict__ rel_emb,
                       const int* __restrict__ labels,
                       const float* __restrict__ w_nt, const float* __restrict__ b_nt)
{
    __shared__ float smr[256];
    if (blockIdx.x < KB) {
        float acc = 0.f;
        for (long idx = (long)blockIdx.x * 256 + threadIdx.x; idx < (long)EE * 16;
             idx += (long)KB * 256) {
            int e = (int)(idx >> 4), q = (int)(idx & 15);
            if (g_mask[e] != 0.f) {
                float4 a = *(const float4*)&g_fx[(long)src[e]*DD + q*4];
                float4 b = *(const float4*)&g_fx[(long)dst[e]*DD + q*4];
                float4 r = *(const float4*)&rel_emb[g_rel[e]*DD + q*4];
                float dx = a.x + r.x - b.x;
                float dy = a.y + r.y - b.y;
                float dz = a.z + r.z - b.z;
                float dw = a.w + r.w - b.w;
                acc += dx*dx + dy*dy + dz*dz + dw*dw;
            }
        }
        smr[threadIdx.x] = acc; __syncthreads();
        for (int s = 128; s > 0; s >>= 1) {
            if (threadIdx.x < s) smr[threadIdx.x] += smr[threadIdx.x + s];
            __syncthreads();
        }
        if (threadIdx.x == 0) atomicAdd(&g_kge, smr[0]);
    } else {
        int n = (blockIdx.x - KB) * 256 + threadIdx.x;
        float loss = 0.f;
        if (n < MM) {
            const float* xr = g_fx + (long)n * DD;
            float z0 = b_nt[0], z1 = b_nt[1], z2 = b_nt[2];
            #pragma unroll 16
            for (int k = 0; k < DD; k++) {
                float v = xr[k];
                z0 += v * w_nt[k*3 + 0];
                z1 += v * w_nt[k*3 + 1];
                z2 += v * w_nt[k*3 + 2];
            }
            float mx  = fmaxf(z0, fmaxf(z1, z2));
            float lse = mx + logf(expf(z0 - mx) + expf(z1 - mx) + expf(z2 - mx));
            int lab = labels[n];
            float zl = (lab == 0) ? z0 : ((lab == 1) ? z1 : z2);
            loss = lse - zl;
        }
        smr[threadIdx.x] = loss; __syncthreads();
        for (int s = 128; s > 0; s >>= 1) {
            if (threadIdx.x < s) smr[threadIdx.x] += smr[threadIdx.x + s];
            __syncthreads();
        }
        if (threadIdx.x == 0) atomicAdd(&g_nt, smr[0]);
    }
}

// ---------------- write loss scalars ----------------
__global__ void k_finalize(float* __restrict__ out, long off)
{
    out[off]     = g_kge / (float)((long)EE * DD);
    out[off + 1] = g_nt / (float)MM;
}

// =====================================================================================
extern "C" void kernel_launch(void* const* d_in, const int* in_sizes, int n_in,
                              void* d_out, int out_size)
{
    const int*   node_ids   = (const int*)  d_in[0];
    const int*   edge_index = (const int*)  d_in[1];
    const float* edge_attr  = (const float*)d_in[2];
    const float* tokemb     = (const float*)d_in[3];
    const int*   labels     = (const int*)  d_in[4];
    const float* kg_emb     = (const float*)d_in[5];
    const float* rel_emb    = (const float*)d_in[6];
    const float* w_e2       = (const float*)d_in[7];
    const float* b_e2       = (const float*)d_in[8];
    const float* att1_w     = (const float*)d_in[9];
    const float* att1_b     = (const float*)d_in[10];
    const float* root1      = (const float*)d_in[11];
    const float* bias1      = (const float*)d_in[12];
    const float* att2_w     = (const float*)d_in[13];
    const float* att2_b     = (const float*)d_in[14];
    const float* root2      = (const float*)d_in[15];
    const float* bias2      = (const float*)d_in[16];
    const float* w_lin1     = (const float*)d_in[17];
    const float* b_lin1     = (const float*)d_in[18];
    const float* w_lin2     = (const float*)d_in[19];
    const float* b_lin2     = (const float*)d_in[20];
    const float* w_nt       = (const float*)d_in[21];
    const float* b_nt       = (const float*)d_in[22];
    float* out = (float*)d_out;

    const int* src = edge_index;
    const int* dst = edge_index + EE;

    void *px_, *ph_, *pfx_, *paggr_, *pu1_, *pu2_, *ps1_, *ps2_;
    void *pb1h_, *pb1l_, *pr1h_, *pr1l_, *pr2h_, *pr2l_;
    cudaGetSymbolAddress(&px_,    g_x);
    cudaGetSymbolAddress(&ph_,    g_h);
    cudaGetSymbolAddress(&pfx_,   g_fx);
    cudaGetSymbolAddress(&paggr_, g_aggr);
    cudaGetSymbolAddress(&pu1_,   g_u1);
    cudaGetSymbolAddress(&pu2_,   g_u2);
    cudaGetSymbolAddress(&ps1_,   g_sum1);
    cudaGetSymbolAddress(&ps2_,   g_sum2);
    cudaGetSymbolAddress(&pb1h_,  g_b1hi);
    cudaGetSymbolAddress(&pb1l_,  g_b1lo);
    cudaGetSymbolAddress(&pr1h_,  g_r1hi);
    cudaGetSymbolAddress(&pr1l_,  g_r1lo);
    cudaGetSymbolAddress(&pr2h_,  g_r2hi);
    cudaGetSymbolAddress(&pr2l_,  g_r2lo);
    float* px    = (float*)px_;
    float* ph    = (float*)ph_;
    float* pfx   = (float*)pfx_;
    float* paggr = (float*)paggr_;
    float* pu1   = (float*)pu1_;
    float* pu2   = (float*)pu2_;
    float* ps1   = (float*)ps1_;
    float* ps2   = (float*)ps2_;

    static cudaStream_t s1 = nullptr, s2 = nullptr;
    static cudaEvent_t eFork, eJ1, eJ2, eFx, eLoss;
    if (!s1) {
        cudaStreamCreateWithFlags(&s1, cudaStreamNonBlocking);
        cudaStreamCreateWithFlags(&s2, cudaStreamNonBlocking);
        cudaEventCreateWithFlags(&eFork, cudaEventDisableTiming);
        cudaEventCreateWithFlags(&eJ1,   cudaEventDisableTiming);
        cudaEventCreateWithFlags(&eJ2,   cudaEventDisableTiming);
        cudaEventCreateWithFlags(&eFx,   cudaEventDisableTiming);
        cudaEventCreateWithFlags(&eLoss, cudaEventDisableTiming);
    }

    // ---- fork prep across 3 streams ----
    cudaEventRecord(eFork, 0);
    cudaStreamWaitEvent(s1, eFork, 0);
    cudaStreamWaitEvent(s2, eFork, 0);

    // s0: zero aggr + gather + scalars; relation ids/mask
    k_init<<<(MM*16 + 255)/256, 256>>>(node_ids, kg_emb);
    k_relmask<<<EB, 256>>>(edge_attr);

    // s1: split weights, zero tok region, split-K token HMMA GEMM -> px[0:TT)
    k_bsplit<<<(DD*TOKN + 2*DD*DD + 255)/256, 256, 0, s1>>>(w_lin1, root1, root2);
    k_zerotok<<<(TT*16 + 255)/256, 256, 0, s1>>>();
    {
        dim3 grid(1, (TT + 127)/128, 4);
        k_mma_n64<0,0,0,1,0><<<grid, 256, 0, s1>>>(
            tokemb, (const __nv_bfloat16*)pb1h_, (const __nv_bfloat16*)pb1l_,
            b_lin1, nullptr, nullptr, px, TT, TOKN, 192);
    }

    // s2: w_lin2 split + fused u-tables
    k_wsplit<<<(TOKN*DD + 255)/256, 256, 0, s2>>>(w_lin2);
    k_ufused<<<DD, 256, 0, s2>>>(rel_emb, w_e2, b_e2, att1_w, att2_w);

    // ---- join ----
    cudaEventRecord(eJ1, s1);
    cudaEventRecord(eJ2, s2);
    cudaStreamWaitEvent(0, eJ1, 0);
    cudaStreamWaitEvent(0, eJ2, 0);

    // ---- layer 1: fused edge phase (unnormalized), GEMM normalizes + adds + relu ----
    k_p<<<(MM + 255)/256, 256>>>(px, att1_w, att1_b);
    k_edgefused<<<(EE + 255)/256, 256>>>(px, pu1, src, dst, ps1);
    {
        dim3 grid(1, (MM + 127)/128, 1);
        k_mma_n64<1,1,1,0,1><<<grid, 256>>>(
            px, (const __nv_bfloat16*)pr1h_, (const __nv_bfloat16*)pr1l_,
            bias1, paggr, ps1, ph, MM, DD, DD);
    }

    // ---- layer 2 ----
    k_p<<<(MM + 255)/256, 256>>>(ph, att2_w, att2_b);
    k_edgefused<<<(EE + 255)/256, 256>>>(ph, pu2, src, dst, ps2);
    {
        dim3 grid(1, (MM + 127)/128, 1);
        k_mma_n64<0,1,0,0,1><<<grid, 256>>>(
            ph, (const __nv_bfloat16*)pr2h_, (const __nv_bfloat16*)pr2l_,
            bias2, paggr, ps2, pfx, MM, DD, DD);
    }

    // ---- fork tail: losses on s1 in parallel with final GEMM ----
    cudaEventRecord(eFx, 0);
    cudaStreamWaitEvent(s1, eFx, 0);
    k_loss<<<KB + (MM + 255)/256, 256, 0, s1>>>(src, dst, rel_emb, labels, w_nt, b_nt);
    k_finalize<<<1, 1, 0, s1>>>(out, (long)out_size - 2);

    {
        dim3 grid(TOKN/64, (MM + 127)/128);
        k_gemm_mma<<<grid, 256>>>(pfx, b_lin2, out);
    }

    cudaEventRecord(eLoss, s1);
    cudaStreamWaitEvent(0, eLoss, 0);
}

// round 16
// speedup vs baseline: 1.2064x; 1.2064x over previous
#include <cuda_runtime.h>
#include <cuda_bf16.h>
#include <stdint.h>
#include <math.h>
#include <float.h>

#define DD   64
#define TT   4096
#define NN   20000
#define MM   24096     // TT + NN
#define EE   100000
#define RR   50
#define TOKN 768

// ---------------- scratch (device globals; no allocation allowed) ----------------
__device__ __align__(16) float g_x[MM*DD];
__device__ __align__(16) float g_h[MM*DD];
__device__ __align__(16) float g_fx[MM*DD];
__device__ __align__(16) float g_aggr[MM*DD];
__device__ __align__(16) float g_u1[RR*DD];
__device__ __align__(16) float g_u2[RR*DD];
__device__ __align__(16) __nv_bfloat16 g_bhi[TOKN*DD];    // w_lin2^T hi [768][64]
__device__ __align__(16) __nv_bfloat16 g_blo[TOKN*DD];    // w_lin2^T lo
__device__ __align__(16) __nv_bfloat16 g_b1hi[DD*TOKN];   // w_lin1^T hi [64][768]
__device__ __align__(16) __nv_bfloat16 g_b1lo[DD*TOKN];
__device__ __align__(16) __nv_bfloat16 g_r1hi[DD*DD];     // root1^T hi [64][64]
__device__ __align__(16) __nv_bfloat16 g_r1lo[DD*DD];
__device__ __align__(16) __nv_bfloat16 g_r2hi[DD*DD];     // root2^T hi
__device__ __align__(16) __nv_bfloat16 g_r2lo[DD*DD];
__device__ int   g_rel[EE];
__device__ float g_mask[EE];
__device__ float g_p[MM];
__device__ float g_logit[EE];
__device__ float g_sum1, g_sum2;
__device__ float g_kge;
__device__ float g_nt;

// ---------------- helpers ----------------
__device__ __forceinline__ uint32_t pack_bf2(float a, float b) {
    __nv_bfloat162 t = __floats2bfloat162_rn(a, b);
    return *(uint32_t*)&t;
}

__device__ __forceinline__ void mma_bf16(float* c, const uint32_t* a,
                                         uint32_t b0, uint32_t b1) {
    asm volatile(
        "mma.sync.aligned.m16n8k16.row.col.f32.bf16.bf16.f32 "
        "{%0,%1,%2,%3}, {%4,%5,%6,%7}, {%8,%9}, {%0,%1,%2,%3};"
        : "+f"(c[0]), "+f"(c[1]), "+f"(c[2]), "+f"(c[3])
        : "r"(a[0]), "r"(a[1]), "r"(a[2]), "r"(a[3]), "r"(b0), "r"(b1));
}

#define BSTR 72   // smem B row stride in bf16

// ================ generic N=64 HMMA split-bf16 GEMM =================================
// C[M,64] = A[M,Kdim] @ B[Kdim,64] (+bias)(+addsrc*inv)(relu)(zero addsrc)(atomic)
template<int RELU, int HASADD, int ZEROADD, int ATOMIC, int SCALEADD>
__global__ void __launch_bounds__(256, 2)
k_mma_n64(const float* __restrict__ A,
          const __nv_bfloat16* __restrict__ Bhi, const __nv_bfloat16* __restrict__ Blo,
          const float* __restrict__ bias, float* __restrict__ addsrc,
          const float* __restrict__ scale,
          float* __restrict__ C, int Mrows, int Kdim, int kPerZ)
{
    __shared__ __nv_bfloat16 smBhi[64 * BSTR];
    __shared__ __nv_bfloat16 smBlo[64 * BSTR];
    int tid  = threadIdx.x;
    int wid  = tid >> 5;
    int lane = tid & 31;
    int g    = lane >> 2;
    int tg   = lane & 3;
    int row0 = blockIdx.y * 128;
    int rbase = row0 + wid * 16;

    float acc[8][4];
    #pragma unroll
    for (int nt = 0; nt < 8; nt++)
        #pragma unroll
        for (int j = 0; j < 4; j++) acc[nt][j] = 0.f;

    int kb = blockIdx.z * kPerZ;
    for (int kc = kb; kc < kb + kPerZ; kc += 64) {
        for (int i = tid; i < 64 * 16; i += 256) {
            int n = i >> 4, q = i & 15;
            uint2 h = *(const uint2*)&Bhi[(long)n * Kdim + kc + q * 4];
            uint2 l = *(const uint2*)&Blo[(long)n * Kdim + kc + q * 4];
            *(uint2*)&smBhi[n * BSTR + q * 4] = h;
            *(uint2*)&smBlo[n * BSTR + q * 4] = l;
        }
        __syncthreads();

        #pragma unroll
        for (int ks = 0; ks < 4; ks++) {
            int k0 = ks * 16;
            uint32_t ahi[4], alo[4];
            #pragma unroll
            for (int i = 0; i < 4; i++) {
                int r = rbase + g + (i & 1) * 8;
                int k = kc + k0 + tg * 2 + (i >> 1) * 8;
                float2 v = make_float2(0.f, 0.f);
                if (r < Mrows) v = *(const float2*)&A[(long)r * Kdim + k];
                float hx = __bfloat162float(__float2bfloat16(v.x));
                float hy = __bfloat162float(__float2bfloat16(v.y));
                ahi[i] = pack_bf2(v.x, v.y);
                alo[i] = pack_bf2(v.x - hx, v.y - hy);
            }
            #pragma unroll
            for (int nt = 0; nt < 8; nt++) {
                int n = nt * 8 + g;
                uint32_t b0h = *(const uint32_t*)&smBhi[n * BSTR + k0 + tg * 2];
                uint32_t b1h = *(const uint32_t*)&smBhi[n * BSTR + k0 + tg * 2 + 8];
                uint32_t b0l = *(const uint32_t*)&smBlo[n * BSTR + k0 + tg * 2];
                uint32_t b1l = *(const uint32_t*)&smBlo[n * BSTR + k0 + tg * 2 + 8];
                mma_bf16(acc[nt], ahi, b0h, b1h);
                mma_bf16(acc[nt], ahi, b0l, b1l);
                mma_bf16(acc[nt], alo, b0h, b1h);
            }
        }
        __syncthreads();
    }

    float inv = 1.f;
    if (SCALEADD) inv = 1.f / *scale;
    bool addbias = !ATOMIC || (blockIdx.z == 0);
    #pragma unroll
    for (int nt = 0; nt < 8; nt++) {
        int c = nt * 8 + tg * 2;
        float2 bv = *(const float2*)&bias[c];
        #pragma unroll
        for (int half = 0; half < 2; half++) {
            int r = rbase + g + half * 8;
            if (r >= Mrows) continue;
            float vx = acc[nt][half*2];
            float vy = acc[nt][half*2 + 1];
            if (addbias) { vx += bv.x; vy += bv.y; }
            if (HASADD) {
                float2 ad = *(float2*)&addsrc[(long)r * 64 + c];
                vx += ad.x * inv; vy += ad.y * inv;
                if (ZEROADD)
                    *(float2*)&addsrc[(long)r * 64 + c] = make_float2(0.f, 0.f);
            }
            if (RELU) { vx = fmaxf(vx, 0.f); vy = fmaxf(vy, 0.f); }
            if (ATOMIC) {
                atomicAdd(&C[(long)r * 64 + c],     vx);
                atomicAdd(&C[(long)r * 64 + c + 1], vy);
            } else {
                *(float2*)&C[(long)r * 64 + c] = make_float2(vx, vy);
            }
        }
    }
}

// ======== final HMMA split-bf16 GEMM: out[M,768] = fx[M,64] @ w_lin2 + bias ========
__global__ void k_wsplit(const float* __restrict__ w_lin2)
{
    int idx = blockIdx.x * blockDim.x + threadIdx.x;
    if (idx >= TOKN * DD) return;
    int n = idx >> 6, k = idx & 63;
    float v = w_lin2[(long)k * TOKN + n];
    __nv_bfloat16 hi = __float2bfloat16(v);
    g_bhi[idx] = hi;
    g_blo[idx] = __float2bfloat16(v - __bfloat162float(hi));
}

// split+transpose w_lin1 [768,64] -> [64][768], root1/root2 [64,64] -> [64][64]
__global__ void k_bsplit(const float* __restrict__ w_lin1,
                         const float* __restrict__ root1,
                         const float* __restrict__ root2)
{
    int idx = blockIdx.x * blockDim.x + threadIdx.x;
    if (idx < DD * TOKN) {
        int n = idx / TOKN, k = idx % TOKN;
        float v = w_lin1[(long)k * DD + n];
        __nv_bfloat16 hi = __float2bfloat16(v);
        g_b1hi[idx] = hi;
        g_b1lo[idx] = __float2bfloat16(v - __bfloat162float(hi));
    } else if (idx < DD * TOKN + DD * DD) {
        int j = idx - DD * TOKN;
        int n = j >> 6, k = j & 63;
        float v = root1[k * DD + n];
        __nv_bfloat16 hi = __float2bfloat16(v);
        g_r1hi[j] = hi;
        g_r1lo[j] = __float2bfloat16(v - __bfloat162float(hi));
    } else if (idx < DD * TOKN + 2 * DD * DD) {
        int j = idx - DD * TOKN - DD * DD;
        int n = j >> 6, k = j & 63;
        float v = root2[k * DD + n];
        __nv_bfloat16 hi = __float2bfloat16(v);
        g_r2hi[j] = hi;
        g_r2lo[j] = __float2bfloat16(v - __bfloat162float(hi));
    }
}

__global__ void __launch_bounds__(256, 2)
k_gemm_mma(const float* __restrict__ A, const float* __restrict__ bias,
           float* __restrict__ out)
{
    __shared__ __nv_bfloat16 smBhi[64 * BSTR];
    __shared__ __nv_bfloat16 smBlo[64 * BSTR];
    int tid  = threadIdx.x;
    int wid  = tid >> 5;
    int lane = tid & 31;
    int g    = lane >> 2;
    int tg   = lane & 3;
    int col0 = blockIdx.x * 64;
    int row0 = blockIdx.y * 128;

    for (int i = tid; i < 64 * 16; i += 256) {
        int n = i >> 4, q = i & 15;
        uint2 h = *(const uint2*)&g_bhi[(long)(col0 + n) * DD + q * 4];
        uint2 l = *(const uint2*)&g_blo[(long)(col0 + n) * DD + q * 4];
        *(uint2*)&smBhi[n * BSTR + q * 4] = h;
        *(uint2*)&smBlo[n * BSTR + q * 4] = l;
    }
    __syncthreads();

    float acc[8][4];
    #pragma unroll
    for (int nt = 0; nt < 8; nt++)
        #pragma unroll
        for (int j = 0; j < 4; j++) acc[nt][j] = 0.f;

    int rbase = row0 + wid * 16;

    #pragma unroll
    for (int ks = 0; ks < 4; ks++) {
        int k0 = ks * 16;
        uint32_t ahi[4], alo[4];
        #pragma unroll
        for (int i = 0; i < 4; i++) {
            int r = rbase + g + (i & 1) * 8;
            int k = k0 + tg * 2 + (i >> 1) * 8;
            float2 v = make_float2(0.f, 0.f);
            if (r < MM) v = *(const float2*)&A[(long)r * DD + k];
            float hx = __bfloat162float(__float2bfloat16(v.x));
            float hy = __bfloat162float(__float2bfloat16(v.y));
            ahi[i] = pack_bf2(v.x, v.y);
            alo[i] = pack_bf2(v.x - hx, v.y - hy);
        }
        #pragma unroll
        for (int nt = 0; nt < 8; nt++) {
            int n = nt * 8 + g;
            uint32_t b0h = *(const uint32_t*)&smBhi[n * BSTR + k0 + tg * 2];
            uint32_t b1h = *(const uint32_t*)&smBhi[n * BSTR + k0 + tg * 2 + 8];
            uint32_t b0l = *(const uint32_t*)&smBlo[n * BSTR + k0 + tg * 2];
            uint32_t b1l = *(const uint32_t*)&smBlo[n * BSTR + k0 + tg * 2 + 8];
            mma_bf16(acc[nt], ahi, b0h, b1h);
            mma_bf16(acc[nt], ahi, b0l, b1l);
            mma_bf16(acc[nt], alo, b0h, b1h);
        }
    }

    #pragma unroll
    for (int nt = 0; nt < 8; nt++) {
        int c = col0 + nt * 8 + tg * 2;
        float2 bv = *(const float2*)&bias[c];
        int r0w = rbase + g;
        if (r0w < MM)
            *(float2*)&out[(long)r0w * TOKN + c] =
                make_float2(acc[nt][0] + bv.x, acc[nt][1] + bv.y);
        int r1w = rbase + g + 8;
        if (r1w < MM)
            *(float2*)&out[(long)r1w * TOKN + c] =
                make_float2(acc[nt][2] + bv.x, acc[nt][3] + bv.y);
    }
}

// ---------------- init: zero aggr, gather kg nodes, reset scalars ----------------
__global__ void k_init(const int* __restrict__ node_ids, const float* __restrict__ kg_emb)
{
    int idx = blockIdx.x * blockDim.x + threadIdx.x;   // float4 units
    float4 z = make_float4(0.f, 0.f, 0.f, 0.f);
    if (idx < MM*16) ((float4*)g_aggr)[idx] = z;
    if (idx < NN*16) {
        int n = idx >> 4, q = idx & 15;
        ((float4*)g_x)[(long)(TT + n)*16 + q] =
            ((const float4*)kg_emb)[(long)node_ids[n]*16 + q];
    }
    if (idx == 0) { g_kge = 0.f; g_nt = 0.f; g_sum1 = 0.f; g_sum2 = 0.f; }
}

// ---------------- zero token region of x ----------------
__global__ void k_zerotok()
{
    int idx = blockIdx.x * blockDim.x + threadIdx.x;
    if (idx < TT*16) ((float4*)g_x)[idx] = make_float4(0.f, 0.f, 0.f, 0.f);
}

// ---------------- relation id + mask (float4 smem staging) ----------------
#define EPB 128
#define EB  ((EE + EPB - 1) / EPB)
__global__ void k_relmask(const float* __restrict__ ea)
{
    __shared__ float smr[EPB * RR];
    int e0 = blockIdx.x * EPB;
    int cnt = min(EPB, EE - e0);
    int total4 = (cnt * RR) >> 2;
    const float4* base4 = (const float4*)(ea + (long)e0 * RR);
    float4* sm4 = (float4*)smr;
    for (int i = threadIdx.x; i < total4; i += 256) sm4[i] = base4[i];
    __syncthreads();
    int el = threadIdx.x;
    if (el < cnt) {
        const float* row = smr + el * RR;
        float acc = 0.f;
        #pragma unroll
        for (int r = 1; r < RR; r++) acc += row[r] * (float)r;
        g_rel[e0 + el] = (int)(acc + 0.5f);
        g_mask[e0 + el] = (row[47] + row[48] + row[49] == 0.f) ? 1.f : 0.f;
    }
}

// ---- fused u-tables ----
__global__ void __launch_bounds__(256)
k_ufused(const float* __restrict__ rel_emb, const float* __restrict__ w_e2,
         const float* __restrict__ b_e2,
         const float* __restrict__ att1_w, const float* __restrict__ att2_w)
{
    __shared__ float ws[64*64];
    __shared__ float re[RR*64];
    int tid = threadIdx.x;
    int d = blockIdx.x;

    for (int i = tid; i < 64*64; i += 256) {
        int k = i >> 6, o = i & 63;
        ws[i] = w_e2[(long)k*4096 + d*64 + o];
    }
    for (int i = tid; i < RR*64; i += 256) re[i] = rel_emb[i];
    __syncthreads();

    int wid = tid >> 5, lane = tid & 31;
    float b1 = b_e2[d*64 + lane];
    float b2 = b_e2[d*64 + lane + 32];
    float w1a = att1_w[64 + lane], w1b = att1_w[64 + lane + 32];
    float w2a = att2_w[64 + lane], w2b = att2_w[64 + lane + 32];

    for (int rel = wid; rel < RR; rel += 8) {
        float acc1 = b1, acc2 = b2;
        const float* rr = re + rel*64;
        #pragma unroll
        for (int k = 0; k < 64; k++) {
            float rv = rr[k];
            acc1 += rv * ws[k*64 + lane];
            acc2 += rv * ws[k*64 + lane + 32];
        }
        acc1 = fmaxf(acc1, 0.f); acc2 = fmaxf(acc2, 0.f);
        float a1 = acc1*w1a + acc2*w1b;
        float a2 = acc1*w2a + acc2*w2b;
        #pragma unroll
        for (int s = 16; s; s >>= 1) {
            a1 += __shfl_down_sync(0xffffffff, a1, s);
            a2 += __shfl_down_sync(0xffffffff, a2, s);
        }
        if (lane == 0) { g_u1[rel*64 + d] = a1; g_u2[rel*64 + d] = a2; }
    }
}

// ---------------- per-node dst-side attention term ----------------
__global__ void k_p(const float* __restrict__ x, const float* __restrict__ att_w,
                    const float* __restrict__ att_b)
{
    int n = blockIdx.x * blockDim.x + threadIdx.x;
    if (n >= MM) return;
    float acc = att_b[0];
    const float4* xr = (const float4*)(x + (long)n * DD);
    const float4* wr = (const float4*)att_w;
    #pragma unroll
    for (int k = 0; k < 16; k++) {
        float4 a = xr[k], w = wr[k];
        acc += a.x*w.x + a.y*w.y + a.z*w.z + a.w*w.w;
    }
    g_p[n] = acc;
}

// ---------------- edge logits -> exp(logit) + global sum ----------------
__global__ void k_logitexp(const float* __restrict__ x, const float* __restrict__ u,
                           const int* __restrict__ src, const int* __restrict__ dst,
                           float* __restrict__ psum)
{
    __shared__ float smr[256];
    int e = blockIdx.x * 256 + threadIdx.x;
    float v = 0.f;
    if (e < EE) {
        float acc = g_p[dst[e]];
        const float4* xr = (const float4*)(x + (long)src[e] * DD);
        const float4* ur = (const float4*)(u + g_rel[e] * DD);
        #pragma unroll
        for (int k = 0; k < 16; k++) {
            float4 a = xr[k], w = ur[k];
            acc += a.x*w.x + a.y*w.y + a.z*w.z + a.w*w.w;
        }
        v = __expf(acc);
        g_logit[e] = v;
    }
    smr[threadIdx.x] = v; __syncthreads();
    for (int s = 128; s > 0; s >>= 1) {
        if (threadIdx.x < s) smr[threadIdx.x] += smr[threadIdx.x + s];
        __syncthreads();
    }
    if (threadIdx.x == 0) atomicAdd(psum, smr[0]);
}

// ------- message scatter, UNNORMALIZED: aggr[dst] += exp(logit) * x[src] -------------
// (coalesced (e,d) indexing; normalization folded into the GEMM epilogue)
__global__ void k_scatter(const float* __restrict__ x, const int* __restrict__ src,
                          const int* __restrict__ dst)
{
    long idx = (long)blockIdx.x * 256 + threadIdx.x;
    if (idx >= (long)EE * DD) return;
    int e = (int)(idx >> 6), d = (int)(idx & 63);
    float a = g_logit[e];
    atomicAdd(&g_aggr[(long)dst[e]*DD + d], x[(long)src[e]*DD + d] * a);
}

// ---------------- fused losses ----------------
#define KB 512
__global__ void k_loss(const int* __restrict__ src, const int* __restrict__ dst,
                       const float* __restrict__ rel_emb,
                       const int* __restrict__ labels,
                       const float* __restrict__ w_nt, const float* __restrict__ b_nt)
{
    __shared__ float smr[256];
    if (blockIdx.x < KB) {
        float acc = 0.f;
        for (long idx = (long)blockIdx.x * 256 + threadIdx.x; idx < (long)EE * 16;
             idx += (long)KB * 256) {
            int e = (int)(idx >> 4), q = (int)(idx & 15);
            if (g_mask[e] != 0.f) {
                float4 a = *(const float4*)&g_fx[(long)src[e]*DD + q*4];
                float4 b = *(const float4*)&g_fx[(long)dst[e]*DD + q*4];
                float4 r = *(const float4*)&rel_emb[g_rel[e]*DD + q*4];
                float dx = a.x + r.x - b.x;
                float dy = a.y + r.y - b.y;
                float dz = a.z + r.z - b.z;
                float dw = a.w + r.w - b.w;
                acc += dx*dx + dy*dy + dz*dz + dw*dw;
            }
        }
        smr[threadIdx.x] = acc; __syncthreads();
        for (int s = 128; s > 0; s >>= 1) {
            if (threadIdx.x < s) smr[threadIdx.x] += smr[threadIdx.x + s];
            __syncthreads();
        }
        if (threadIdx.x == 0) atomicAdd(&g_kge, smr[0]);
    } else {
        int n = (blockIdx.x - KB) * 256 + threadIdx.x;
        float loss = 0.f;
        if (n < MM) {
            const float* xr = g_fx + (long)n * DD;
            float z0 = b_nt[0], z1 = b_nt[1], z2 = b_nt[2];
            #pragma unroll 16
            for (int k = 0; k < DD; k++) {
                float v = xr[k];
                z0 += v * w_nt[k*3 + 0];
                z1 += v * w_nt[k*3 + 1];
                z2 += v * w_nt[k*3 + 2];
            }
            float mx  = fmaxf(z0, fmaxf(z1, z2));
            float lse = mx + logf(expf(z0 - mx) + expf(z1 - mx) + expf(z2 - mx));
            int lab = labels[n];
            float zl = (lab == 0) ? z0 : ((lab == 1) ? z1 : z2);
            loss = lse - zl;
        }
        smr[threadIdx.x] = loss; __syncthreads();
        for (int s = 128; s > 0; s >>= 1) {
            if (threadIdx.x < s) smr[threadIdx.x] += smr[threadIdx.x + s];
            __syncthreads();
        }
        if (threadIdx.x == 0) atomicAdd(&g_nt, smr[0]);
    }
}

// ---------------- write loss scalars ----------------
__global__ void k_finalize(float* __restrict__ out, long off)
{
    out[off]     = g_kge / (float)((long)EE * DD);
    out[off + 1] = g_nt / (float)MM;
}

// =====================================================================================
extern "C" void kernel_launch(void* const* d_in, const int* in_sizes, int n_in,
                              void* d_out, int out_size)
{
    const int*   node_ids   = (const int*)  d_in[0];
    const int*   edge_index = (const int*)  d_in[1];
    const float* edge_attr  = (const float*)d_in[2];
    const float* tokemb     = (const float*)d_in[3];
    const int*   labels     = (const int*)  d_in[4];
    const float* kg_emb     = (const float*)d_in[5];
    const float* rel_emb    = (const float*)d_in[6];
    const float* w_e2       = (const float*)d_in[7];
    const float* b_e2       = (const float*)d_in[8];
    const float* att1_w     = (const float*)d_in[9];
    const float* att1_b     = (const float*)d_in[10];
    const float* root1      = (const float*)d_in[11];
    const float* bias1      = (const float*)d_in[12];
    const float* att2_w     = (const float*)d_in[13];
    const float* att2_b     = (const float*)d_in[14];
    const float* root2      = (const float*)d_in[15];
    const float* bias2      = (const float*)d_in[16];
    const float* w_lin1     = (const float*)d_in[17];
    const float* b_lin1     = (const float*)d_in[18];
    const float* w_lin2     = (const float*)d_in[19];
    const float* b_lin2     = (const float*)d_in[20];
    const float* w_nt       = (const float*)d_in[21];
    const float* b_nt       = (const float*)d_in[22];
    float* out = (float*)d_out;

    const int* src = edge_index;
    const int* dst = edge_index + EE;

    void *px_, *ph_, *pfx_, *paggr_, *pu1_, *pu2_, *ps1_, *ps2_;
    void *pb1h_, *pb1l_, *pr1h_, *pr1l_, *pr2h_, *pr2l_;
    cudaGetSymbolAddress(&px_,    g_x);
    cudaGetSymbolAddress(&ph_,    g_h);
    cudaGetSymbolAddress(&pfx_,   g_fx);
    cudaGetSymbolAddress(&paggr_, g_aggr);
    cudaGetSymbolAddress(&pu1_,   g_u1);
    cudaGetSymbolAddress(&pu2_,   g_u2);
    cudaGetSymbolAddress(&ps1_,   g_sum1);
    cudaGetSymbolAddress(&ps2_,   g_sum2);
    cudaGetSymbolAddress(&pb1h_,  g_b1hi);
    cudaGetSymbolAddress(&pb1l_,  g_b1lo);
    cudaGetSymbolAddress(&pr1h_,  g_r1hi);
    cudaGetSymbolAddress(&pr1l_,  g_r1lo);
    cudaGetSymbolAddress(&pr2h_,  g_r2hi);
    cudaGetSymbolAddress(&pr2l_,  g_r2lo);
    float* px    = (float*)px_;
    float* ph    = (float*)ph_;
    float* pfx   = (float*)pfx_;
    float* paggr = (float*)paggr_;
    float* pu1   = (float*)pu1_;
    float* pu2   = (float*)pu2_;
    float* ps1   = (float*)ps1_;
    float* ps2   = (float*)ps2_;

    static cudaStream_t s1 = nullptr, s2 = nullptr;
    static cudaEvent_t eFork, eJ1, eJ2, eFx, eLoss;
    if (!s1) {
        cudaStreamCreateWithFlags(&s1, cudaStreamNonBlocking);
        cudaStreamCreateWithFlags(&s2, cudaStreamNonBlocking);
        cudaEventCreateWithFlags(&eFork, cudaEventDisableTiming);
        cudaEventCreateWithFlags(&eJ1,   cudaEventDisableTiming);
        cudaEventCreateWithFlags(&eJ2,   cudaEventDisableTiming);
        cudaEventCreateWithFlags(&eFx,   cudaEventDisableTiming);
        cudaEventCreateWithFlags(&eLoss, cudaEventDisableTiming);
    }

    // ---- fork prep across 3 streams ----
    cudaEventRecord(eFork, 0);
    cudaStreamWaitEvent(s1, eFork, 0);
    cudaStreamWaitEvent(s2, eFork, 0);

    // s0: zero aggr + gather + scalars; relation ids/mask
    k_init<<<(MM*16 + 255)/256, 256>>>(node_ids, kg_emb);
    k_relmask<<<EB, 256>>>(edge_attr);

    // s1: split weights, zero tok region, split-K token HMMA GEMM -> px[0:TT)
    k_bsplit<<<(DD*TOKN + 2*DD*DD + 255)/256, 256, 0, s1>>>(w_lin1, root1, root2);
    k_zerotok<<<(TT*16 + 255)/256, 256, 0, s1>>>();
    {
        dim3 grid(1, (TT + 127)/128, 4);
        k_mma_n64<0,0,0,1,0><<<grid, 256, 0, s1>>>(
            tokemb, (const __nv_bfloat16*)pb1h_, (const __nv_bfloat16*)pb1l_,
            b_lin1, nullptr, nullptr, px, TT, TOKN, 192);
    }

    // s2: w_lin2 split + fused u-tables
    k_wsplit<<<(TOKN*DD + 255)/256, 256, 0, s2>>>(w_lin2);
    k_ufused<<<DD, 256, 0, s2>>>(rel_emb, w_e2, b_e2, att1_w, att2_w);

    // ---- join ----
    cudaEventRecord(eJ1, s1);
    cudaEventRecord(eJ2, s2);
    cudaStreamWaitEvent(0, eJ1, 0);
    cudaStreamWaitEvent(0, eJ2, 0);

    // ---- layer 1: edge phase (unnormalized scatter), GEMM normalizes + adds + relu ----
    k_p<<<(MM + 255)/256, 256>>>(px, att1_w, att1_b);
    k_logitexp<<<(EE + 255)/256, 256>>>(px, pu1, src, dst, ps1);
    k_scatter<<<(int)(((long)EE*DD + 255)/256), 256>>>(px, src, dst);
    {
        dim3 grid(1, (MM + 127)/128, 1);
        k_mma_n64<1,1,1,0,1><<<grid, 256>>>(
            px, (const __nv_bfloat16*)pr1h_, (const __nv_bfloat16*)pr1l_,
            bias1, paggr, ps1, ph, MM, DD, DD);
    }

    // ---- layer 2 ----
    k_p<<<(MM + 255)/256, 256>>>(ph, att2_w, att2_b);
    k_logitexp<<<(EE + 255)/256, 256>>>(ph, pu2, src, dst, ps2);
    k_scatter<<<(int)(((long)EE*DD + 255)/256), 256>>>(ph, src, dst);
    {
        dim3 grid(1, (MM + 127)/128, 1);
        k_mma_n64<0,1,0,0,1><<<grid, 256>>>(
            ph, (const __nv_bfloat16*)pr2h_, (const __nv_bfloat16*)pr2l_,
            bias2, paggr, ps2, pfx, MM, DD, DD);
    }

    // ---- fork tail: losses on s1 in parallel with final GEMM ----
    cudaEventRecord(eFx, 0);
    cudaStreamWaitEvent(s1, eFx, 0);
    k_loss<<<KB + (MM + 255)/256, 256, 0, s1>>>(src, dst, rel_emb, labels, w_nt, b_nt);
    k_finalize<<<1, 1, 0, s1>>>(out, (long)out_size - 2);

    {
        dim3 grid(TOKN/64, (MM + 127)/128);
        k_gemm_mma<<<grid, 256>>>(pfx, b_lin2, out);
    }

    cudaEventRecord(eLoss, s1);
    cudaStreamWaitEvent(0, eLoss, 0);
}

// round 17
// speedup vs baseline: 1.2894x; 1.0688x over previous
#include <cuda_runtime.h>
#include <cuda_bf16.h>
#include <stdint.h>
#include <math.h>
#include <float.h>

#define DD   64
#define TT   4096
#define NN   20000
#define MM   24096     // TT + NN
#define EE   100000
#define RR   50
#define TOKN 768

// ---------------- scratch (device globals; no allocation allowed) ----------------
__device__ __align__(16) float g_x[MM*DD];
__device__ __align__(16) float g_h[MM*DD];
__device__ __align__(16) float g_fx[MM*DD];
__device__ __align__(16) float g_aggr[MM*DD];
__device__ __align__(16) float g_u1[RR*DD];
__device__ __align__(16) float g_u2[RR*DD];
__device__ __align__(16) __nv_bfloat16 g_bhi[TOKN*DD];    // w_lin2^T hi [768][64]
__device__ __align__(16) __nv_bfloat16 g_blo[TOKN*DD];    // w_lin2^T lo
__device__ __align__(16) __nv_bfloat16 g_b1hi[DD*TOKN];   // w_lin1^T hi [64][768]
__device__ __align__(16) __nv_bfloat16 g_b1lo[DD*TOKN];
__device__ __align__(16) __nv_bfloat16 g_r1hi[DD*DD];     // root1^T hi [64][64]
__device__ __align__(16) __nv_bfloat16 g_r1lo[DD*DD];
__device__ __align__(16) __nv_bfloat16 g_r2hi[DD*DD];     // root2^T hi
__device__ __align__(16) __nv_bfloat16 g_r2lo[DD*DD];
__device__ int   g_rel[EE];
__device__ float g_mask[EE];
__device__ float g_p[MM];
__device__ float g_logit[EE];
__device__ float g_sum1, g_sum2;
__device__ float g_kge;
__device__ float g_nt;

// ---------------- helpers ----------------
__device__ __forceinline__ uint32_t pack_bf2(float a, float b) {
    __nv_bfloat162 t = __floats2bfloat162_rn(a, b);
    return *(uint32_t*)&t;
}

__device__ __forceinline__ void mma_bf16(float* c, const uint32_t* a,
                                         uint32_t b0, uint32_t b1) {
    asm volatile(
        "mma.sync.aligned.m16n8k16.row.col.f32.bf16.bf16.f32 "
        "{%0,%1,%2,%3}, {%4,%5,%6,%7}, {%8,%9}, {%0,%1,%2,%3};"
        : "+f"(c[0]), "+f"(c[1]), "+f"(c[2]), "+f"(c[3])
        : "r"(a[0]), "r"(a[1]), "r"(a[2]), "r"(a[3]), "r"(b0), "r"(b1));
}

__device__ __forceinline__ void redAdd2(float* p, float a, float b) {
    asm volatile("red.global.add.v2.f32 [%0], {%1, %2};"
                 :: "l"(p), "f"(a), "f"(b) : "memory");
}

#define BSTR 72   // smem B row stride in bf16

// ================ generic N=64 HMMA split-bf16 GEMM =================================
// C[M,64] = A[M,Kdim] @ B[Kdim,64] (+bias)(+addsrc*inv)(relu)(zero addsrc)(atomic)
template<int RELU, int HASADD, int ZEROADD, int ATOMIC, int SCALEADD>
__global__ void __launch_bounds__(256, 2)
k_mma_n64(const float* __restrict__ A,
          const __nv_bfloat16* __restrict__ Bhi, const __nv_bfloat16* __restrict__ Blo,
          const float* __restrict__ bias, float* __restrict__ addsrc,
          const float* __restrict__ scale,
          float* __restrict__ C, int Mrows, int Kdim, int kPerZ)
{
    __shared__ __nv_bfloat16 smBhi[64 * BSTR];
    __shared__ __nv_bfloat16 smBlo[64 * BSTR];
    int tid  = threadIdx.x;
    int wid  = tid >> 5;
    int lane = tid & 31;
    int g    = lane >> 2;
    int tg   = lane & 3;
    int row0 = blockIdx.y * 128;
    int rbase = row0 + wid * 16;

    float acc[8][4];
    #pragma unroll
    for (int nt = 0; nt < 8; nt++)
        #pragma unroll
        for (int j = 0; j < 4; j++) acc[nt][j] = 0.f;

    int kb = blockIdx.z * kPerZ;
    for (int kc = kb; kc < kb + kPerZ; kc += 64) {
        for (int i = tid; i < 64 * 16; i += 256) {
            int n = i >> 4, q = i & 15;
            uint2 h = *(const uint2*)&Bhi[(long)n * Kdim + kc + q * 4];
            uint2 l = *(const uint2*)&Blo[(long)n * Kdim + kc + q * 4];
            *(uint2*)&smBhi[n * BSTR + q * 4] = h;
            *(uint2*)&smBlo[n * BSTR + q * 4] = l;
        }
        __syncthreads();

        #pragma unroll
        for (int ks = 0; ks < 4; ks++) {
            int k0 = ks * 16;
            uint32_t ahi[4], alo[4];
            #pragma unroll
            for (int i = 0; i < 4; i++) {
                int r = rbase + g + (i & 1) * 8;
                int k = kc + k0 + tg * 2 + (i >> 1) * 8;
                float2 v = make_float2(0.f, 0.f);
                if (r < Mrows) v = *(const float2*)&A[(long)r * Kdim + k];
                float hx = __bfloat162float(__float2bfloat16(v.x));
                float hy = __bfloat162float(__float2bfloat16(v.y));
                ahi[i] = pack_bf2(v.x, v.y);
                alo[i] = pack_bf2(v.x - hx, v.y - hy);
            }
            #pragma unroll
            for (int nt = 0; nt < 8; nt++) {
                int n = nt * 8 + g;
                uint32_t b0h = *(const uint32_t*)&smBhi[n * BSTR + k0 + tg * 2];
                uint32_t b1h = *(const uint32_t*)&smBhi[n * BSTR + k0 + tg * 2 + 8];
                uint32_t b0l = *(const uint32_t*)&smBlo[n * BSTR + k0 + tg * 2];
                uint32_t b1l = *(const uint32_t*)&smBlo[n * BSTR + k0 + tg * 2 + 8];
                mma_bf16(acc[nt], ahi, b0h, b1h);
                mma_bf16(acc[nt], ahi, b0l, b1l);
                mma_bf16(acc[nt], alo, b0h, b1h);
            }
        }
        __syncthreads();
    }

    float inv = 1.f;
    if (SCALEADD) inv = 1.f / *scale;
    bool addbias = !ATOMIC || (blockIdx.z == 0);
    #pragma unroll
    for (int nt = 0; nt < 8; nt++) {
        int c = nt * 8 + tg * 2;
        float2 bv = *(const float2*)&bias[c];
        #pragma unroll
        for (int half = 0; half < 2; half++) {
            int r = rbase + g + half * 8;
            if (r >= Mrows) continue;
            float vx = acc[nt][half*2];
            float vy = acc[nt][half*2 + 1];
            if (addbias) { vx += bv.x; vy += bv.y; }
            if (HASADD) {
                float2 ad = *(float2*)&addsrc[(long)r * 64 + c];
                vx += ad.x * inv; vy += ad.y * inv;
                if (ZEROADD)
                    *(float2*)&addsrc[(long)r * 64 + c] = make_float2(0.f, 0.f);
            }
            if (RELU) { vx = fmaxf(vx, 0.f); vy = fmaxf(vy, 0.f); }
            if (ATOMIC) {
                atomicAdd(&C[(long)r * 64 + c],     vx);
                atomicAdd(&C[(long)r * 64 + c + 1], vy);
            } else {
                *(float2*)&C[(long)r * 64 + c] = make_float2(vx, vy);
            }
        }
    }
}

// ======== final HMMA split-bf16 GEMM: out[M,768] = fx[M,64] @ w_lin2 + bias ========
__global__ void k_wsplit(const float* __restrict__ w_lin2)
{
    int idx = blockIdx.x * blockDim.x + threadIdx.x;
    if (idx >= TOKN * DD) return;
    int n = idx >> 6, k = idx & 63;
    float v = w_lin2[(long)k * TOKN + n];
    __nv_bfloat16 hi = __float2bfloat16(v);
    g_bhi[idx] = hi;
    g_blo[idx] = __float2bfloat16(v - __bfloat162float(hi));
}

// split+transpose w_lin1 [768,64] -> [64][768], root1/root2 [64,64] -> [64][64]
__global__ void k_bsplit(const float* __restrict__ w_lin1,
                         const float* __restrict__ root1,
                         const float* __restrict__ root2)
{
    int idx = blockIdx.x * blockDim.x + threadIdx.x;
    if (idx < DD * TOKN) {
        int n = idx / TOKN, k = idx % TOKN;
        float v = w_lin1[(long)k * DD + n];
        __nv_bfloat16 hi = __float2bfloat16(v);
        g_b1hi[idx] = hi;
        g_b1lo[idx] = __float2bfloat16(v - __bfloat162float(hi));
    } else if (idx < DD * TOKN + DD * DD) {
        int j = idx - DD * TOKN;
        int n = j >> 6, k = j & 63;
        float v = root1[k * DD + n];
        __nv_bfloat16 hi = __float2bfloat16(v);
        g_r1hi[j] = hi;
        g_r1lo[j] = __float2bfloat16(v - __bfloat162float(hi));
    } else if (idx < DD * TOKN + 2 * DD * DD) {
        int j = idx - DD * TOKN - DD * DD;
        int n = j >> 6, k = j & 63;
        float v = root2[k * DD + n];
        __nv_bfloat16 hi = __float2bfloat16(v);
        g_r2hi[j] = hi;
        g_r2lo[j] = __float2bfloat16(v - __bfloat162float(hi));
    }
}

__global__ void __launch_bounds__(256, 2)
k_gemm_mma(const float* __restrict__ A, const float* __restrict__ bias,
           float* __restrict__ out)
{
    __shared__ __nv_bfloat16 smBhi[64 * BSTR];
    __shared__ __nv_bfloat16 smBlo[64 * BSTR];
    int tid  = threadIdx.x;
    int wid  = tid >> 5;
    int lane = tid & 31;
    int g    = lane >> 2;
    int tg   = lane & 3;
    int col0 = blockIdx.x * 64;
    int row0 = blockIdx.y * 128;

    for (int i = tid; i < 64 * 16; i += 256) {
        int n = i >> 4, q = i & 15;
        uint2 h = *(const uint2*)&g_bhi[(long)(col0 + n) * DD + q * 4];
        uint2 l = *(const uint2*)&g_blo[(long)(col0 + n) * DD + q * 4];
        *(uint2*)&smBhi[n * BSTR + q * 4] = h;
        *(uint2*)&smBlo[n * BSTR + q * 4] = l;
    }
    __syncthreads();

    float acc[8][4];
    #pragma unroll
    for (int nt = 0; nt < 8; nt++)
        #pragma unroll
        for (int j = 0; j < 4; j++) acc[nt][j] = 0.f;

    int rbase = row0 + wid * 16;

    #pragma unroll
    for (int ks = 0; ks < 4; ks++) {
        int k0 = ks * 16;
        uint32_t ahi[4], alo[4];
        #pragma unroll
        for (int i = 0; i < 4; i++) {
            int r = rbase + g + (i & 1) * 8;
            int k = k0 + tg * 2 + (i >> 1) * 8;
            float2 v = make_float2(0.f, 0.f);
            if (r < MM) v = *(const float2*)&A[(long)r * DD + k];
            float hx = __bfloat162float(__float2bfloat16(v.x));
            float hy = __bfloat162float(__float2bfloat16(v.y));
            ahi[i] = pack_bf2(v.x, v.y);
            alo[i] = pack_bf2(v.x - hx, v.y - hy);
        }
        #pragma unroll
        for (int nt = 0; nt < 8; nt++) {
            int n = nt * 8 + g;
            uint32_t b0h = *(const uint32_t*)&smBhi[n * BSTR + k0 + tg * 2];
            uint32_t b1h = *(const uint32_t*)&smBhi[n * BSTR + k0 + tg * 2 + 8];
            uint32_t b0l = *(const uint32_t*)&smBlo[n * BSTR + k0 + tg * 2];
            uint32_t b1l = *(const uint32_t*)&smBlo[n * BSTR + k0 + tg * 2 + 8];
            mma_bf16(acc[nt], ahi, b0h, b1h);
            mma_bf16(acc[nt], ahi, b0l, b1l);
            mma_bf16(acc[nt], alo, b0h, b1h);
        }
    }

    #pragma unroll
    for (int nt = 0; nt < 8; nt++) {
        int c = col0 + nt * 8 + tg * 2;
        float2 bv = *(const float2*)&bias[c];
        int r0w = rbase + g;
        if (r0w < MM)
            *(float2*)&out[(long)r0w * TOKN + c] =
                make_float2(acc[nt][0] + bv.x, acc[nt][1] + bv.y);
        int r1w = rbase + g + 8;
        if (r1w < MM)
            *(float2*)&out[(long)r1w * TOKN + c] =
                make_float2(acc[nt][2] + bv.x, acc[nt][3] + bv.y);
    }
}

// ---------------- init: zero aggr, gather kg nodes, reset scalars ----------------
__global__ void k_init(const int* __restrict__ node_ids, const float* __restrict__ kg_emb)
{
    int idx = blockIdx.x * blockDim.x + threadIdx.x;   // float4 units
    float4 z = make_float4(0.f, 0.f, 0.f, 0.f);
    if (idx < MM*16) ((float4*)g_aggr)[idx] = z;
    if (idx < NN*16) {
        int n = idx >> 4, q = idx & 15;
        ((float4*)g_x)[(long)(TT + n)*16 + q] =
            ((const float4*)kg_emb)[(long)node_ids[n]*16 + q];
    }
    if (idx == 0) { g_kge = 0.f; g_nt = 0.f; g_sum1 = 0.f; g_sum2 = 0.f; }
}

// ---------------- zero token region of x ----------------
__global__ void k_zerotok()
{
    int idx = blockIdx.x * blockDim.x + threadIdx.x;
    if (idx < TT*16) ((float4*)g_x)[idx] = make_float4(0.f, 0.f, 0.f, 0.f);
}

// ---------------- relation id + mask (float4 smem staging) ----------------
#define EPB 128
#define EB  ((EE + EPB - 1) / EPB)
__global__ void k_relmask(const float* __restrict__ ea)
{
    __shared__ float smr[EPB * RR];
    int e0 = blockIdx.x * EPB;
    int cnt = min(EPB, EE - e0);
    int total4 = (cnt * RR) >> 2;
    const float4* base4 = (const float4*)(ea + (long)e0 * RR);
    float4* sm4 = (float4*)smr;
    for (int i = threadIdx.x; i < total4; i += 256) sm4[i] = base4[i];
    __syncthreads();
    int el = threadIdx.x;
    if (el < cnt) {
        const float* row = smr + el * RR;
        float acc = 0.f;
        #pragma unroll
        for (int r = 1; r < RR; r++) acc += row[r] * (float)r;
        g_rel[e0 + el] = (int)(acc + 0.5f);
        g_mask[e0 + el] = (row[47] + row[48] + row[49] == 0.f) ? 1.f : 0.f;
    }
}

// ---- fused u-tables ----
__global__ void __launch_bounds__(256)
k_ufused(const float* __restrict__ rel_emb, const float* __restrict__ w_e2,
         const float* __restrict__ b_e2,
         const float* __restrict__ att1_w, const float* __restrict__ att2_w)
{
    __shared__ float ws[64*64];
    __shared__ float re[RR*64];
    int tid = threadIdx.x;
    int d = blockIdx.x;

    for (int i = tid; i < 64*64; i += 256) {
        int k = i >> 6, o = i & 63;
        ws[i] = w_e2[(long)k*4096 + d*64 + o];
    }
    for (int i = tid; i < RR*64; i += 256) re[i] = rel_emb[i];
    __syncthreads();

    int wid = tid >> 5, lane = tid & 31;
    float b1 = b_e2[d*64 + lane];
    float b2 = b_e2[d*64 + lane + 32];
    float w1a = att1_w[64 + lane], w1b = att1_w[64 + lane + 32];
    float w2a = att2_w[64 + lane], w2b = att2_w[64 + lane + 32];

    for (int rel = wid; rel < RR; rel += 8) {
        float acc1 = b1, acc2 = b2;
        const float* rr = re + rel*64;
        #pragma unroll
        for (int k = 0; k < 64; k++) {
            float rv = rr[k];
            acc1 += rv * ws[k*64 + lane];
            acc2 += rv * ws[k*64 + lane + 32];
        }
        acc1 = fmaxf(acc1, 0.f); acc2 = fmaxf(acc2, 0.f);
        float a1 = acc1*w1a + acc2*w1b;
        float a2 = acc1*w2a + acc2*w2b;
        #pragma unroll
        for (int s = 16; s; s >>= 1) {
            a1 += __shfl_down_sync(0xffffffff, a1, s);
            a2 += __shfl_down_sync(0xffffffff, a2, s);
        }
        if (lane == 0) { g_u1[rel*64 + d] = a1; g_u2[rel*64 + d] = a2; }
    }
}

// ---------------- per-node dst-side attention term ----------------
__global__ void k_p(const float* __restrict__ x, const float* __restrict__ att_w,
                    const float* __restrict__ att_b)
{
    int n = blockIdx.x * blockDim.x + threadIdx.x;
    if (n >= MM) return;
    float acc = att_b[0];
    const float4* xr = (const float4*)(x + (long)n * DD);
    const float4* wr = (const float4*)att_w;
    #pragma unroll
    for (int k = 0; k < 16; k++) {
        float4 a = xr[k], w = wr[k];
        acc += a.x*w.x + a.y*w.y + a.z*w.z + a.w*w.w;
    }
    g_p[n] = acc;
}

// ---------------- edge logits -> exp(logit) + global sum ----------------
__global__ void k_logitexp(const float* __restrict__ x, const float* __restrict__ u,
                           const int* __restrict__ src, const int* __restrict__ dst,
                           float* __restrict__ psum)
{
    __shared__ float smr[256];
    int e = blockIdx.x * 256 + threadIdx.x;
    float v = 0.f;
    if (e < EE) {
        float acc = g_p[dst[e]];
        const float4* xr = (const float4*)(x + (long)src[e] * DD);
        const float4* ur = (const float4*)(u + g_rel[e] * DD);
        #pragma unroll
        for (int k = 0; k < 16; k++) {
            float4 a = xr[k], w = ur[k];
            acc += a.x*w.x + a.y*w.y + a.z*w.z + a.w*w.w;
        }
        v = __expf(acc);
        g_logit[e] = v;
    }
    smr[threadIdx.x] = v; __syncthreads();
    for (int s = 128; s > 0; s >>= 1) {
        if (threadIdx.x < s) smr[threadIdx.x] += smr[threadIdx.x + s];
        __syncthreads();
    }
    if (threadIdx.x == 0) atomicAdd(psum, smr[0]);
}

// ------- message scatter, UNNORMALIZED, v2 (64-bit) vector REDs ----------------------
// aggr[dst] += exp(logit) * x[src]; normalization folded into GEMM epilogue.
__global__ void k_scatter(const float* __restrict__ x, const int* __restrict__ src,
                          const int* __restrict__ dst)
{
    int idx = blockIdx.x * 256 + threadIdx.x;   // over EE*32 float2 units
    if (idx >= EE * 32) return;
    int e = idx >> 5, d2 = idx & 31;
    float a = g_logit[e];
    float2 v = *(const float2*)&x[(long)src[e]*DD + d2*2];
    redAdd2(&g_aggr[(long)dst[e]*DD + d2*2], v.x * a, v.y * a);
}

// ---------------- fused losses ----------------
#define KB 512
__global__ void k_loss(const int* __restrict__ src, const int* __restrict__ dst,
                       const float* __restrict__ rel_emb,
                       const int* __restrict__ labels,
                       const float* __restrict__ w_nt, const float* __restrict__ b_nt)
{
    __shared__ float smr[256];
    if (blockIdx.x < KB) {
        float acc = 0.f;
        for (long idx = (long)blockIdx.x * 256 + threadIdx.x; idx < (long)EE * 16;
             idx += (long)KB * 256) {
            int e = (int)(idx >> 4), q = (int)(idx & 15);
            if (g_mask[e] != 0.f) {
                float4 a = *(const float4*)&g_fx[(long)src[e]*DD + q*4];
                float4 b = *(const float4*)&g_fx[(long)dst[e]*DD + q*4];
                float4 r = *(const float4*)&rel_emb[g_rel[e]*DD + q*4];
                float dx = a.x + r.x - b.x;
                float dy = a.y + r.y - b.y;
                float dz = a.z + r.z - b.z;
                float dw = a.w + r.w - b.w;
                acc += dx*dx + dy*dy + dz*dz + dw*dw;
            }
        }
        smr[threadIdx.x] = acc; __syncthreads();
        for (int s = 128; s > 0; s >>= 1) {
            if (threadIdx.x < s) smr[threadIdx.x] += smr[threadIdx.x + s];
            __syncthreads();
        }
        if (threadIdx.x == 0) atomicAdd(&g_kge, smr[0]);
    } else {
        int n = (blockIdx.x - KB) * 256 + threadIdx.x;
        float loss = 0.f;
        if (n < MM) {
            const float* xr = g_fx + (long)n * DD;
            float z0 = b_nt[0], z1 = b_nt[1], z2 = b_nt[2];
            #pragma unroll 16
            for (int k = 0; k < DD; k++) {
                float v = xr[k];
                z0 += v * w_nt[k*3 + 0];
                z1 += v * w_nt[k*3 + 1];
                z2 += v * w_nt[k*3 + 2];
            }
            float mx  = fmaxf(z0, fmaxf(z1, z2));
            float lse = mx + logf(expf(z0 - mx) + expf(z1 - mx) + expf(z2 - mx));
            int lab = labels[n];
            float zl = (lab == 0) ? z0 : ((lab == 1) ? z1 : z2);
            loss = lse - zl;
        }
        smr[threadIdx.x] = loss; __syncthreads();
        for (int s = 128; s > 0; s >>= 1) {
            if (threadIdx.x < s) smr[threadIdx.x] += smr[threadIdx.x + s];
            __syncthreads();
        }
        if (threadIdx.x == 0) atomicAdd(&g_nt, smr[0]);
    }
}

// ---------------- write loss scalars ----------------
__global__ void k_finalize(float* __restrict__ out, long off)
{
    out[off]     = g_kge / (float)((long)EE * DD);
    out[off + 1] = g_nt / (float)MM;
}

// =====================================================================================
extern "C" void kernel_launch(void* const* d_in, const int* in_sizes, int n_in,
                              void* d_out, int out_size)
{
    const int*   node_ids   = (const int*)  d_in[0];
    const int*   edge_index = (const int*)  d_in[1];
    const float* edge_attr  = (const float*)d_in[2];
    const float* tokemb     = (const float*)d_in[3];
    const int*   labels     = (const int*)  d_in[4];
    const float* kg_emb     = (const float*)d_in[5];
    const float* rel_emb    = (const float*)d_in[6];
    const float* w_e2       = (const float*)d_in[7];
    const float* b_e2       = (const float*)d_in[8];
    const float* att1_w     = (const float*)d_in[9];
    const float* att1_b     = (const float*)d_in[10];
    const float* root1      = (const float*)d_in[11];
    const float* bias1      = (const float*)d_in[12];
    const float* att2_w     = (const float*)d_in[13];
    const float* att2_b     = (const float*)d_in[14];
    const float* root2      = (const float*)d_in[15];
    const float* bias2      = (const float*)d_in[16];
    const float* w_lin1     = (const float*)d_in[17];
    const float* b_lin1     = (const float*)d_in[18];
    const float* w_lin2     = (const float*)d_in[19];
    const float* b_lin2     = (const float*)d_in[20];
    const float* w_nt       = (const float*)d_in[21];
    const float* b_nt       = (const float*)d_in[22];
    float* out = (float*)d_out;

    const int* src = edge_index;
    const int* dst = edge_index + EE;

    void *px_, *ph_, *pfx_, *paggr_, *pu1_, *pu2_, *ps1_, *ps2_;
    void *pb1h_, *pb1l_, *pr1h_, *pr1l_, *pr2h_, *pr2l_;
    cudaGetSymbolAddress(&px_,    g_x);
    cudaGetSymbolAddress(&ph_,    g_h);
    cudaGetSymbolAddress(&pfx_,   g_fx);
    cudaGetSymbolAddress(&paggr_, g_aggr);
    cudaGetSymbolAddress(&pu1_,   g_u1);
    cudaGetSymbolAddress(&pu2_,   g_u2);
    cudaGetSymbolAddress(&ps1_,   g_sum1);
    cudaGetSymbolAddress(&ps2_,   g_sum2);
    cudaGetSymbolAddress(&pb1h_,  g_b1hi);
    cudaGetSymbolAddress(&pb1l_,  g_b1lo);
    cudaGetSymbolAddress(&pr1h_,  g_r1hi);
    cudaGetSymbolAddress(&pr1l_,  g_r1lo);
    cudaGetSymbolAddress(&pr2h_,  g_r2hi);
    cudaGetSymbolAddress(&pr2l_,  g_r2lo);
    float* px    = (float*)px_;
    float* ph    = (float*)ph_;
    float* pfx   = (float*)pfx_;
    float* paggr = (float*)paggr_;
    float* pu1   = (float*)pu1_;
    float* pu2   = (float*)pu2_;
    float* ps1   = (float*)ps1_;
    float* ps2   = (float*)ps2_;

    static cudaStream_t s1 = nullptr, s2 = nullptr;
    static cudaEvent_t eFork, eJ1, eJ2, eFx, eLoss;
    if (!s1) {
        cudaStreamCreateWithFlags(&s1, cudaStreamNonBlocking);
        cudaStreamCreateWithFlags(&s2, cudaStreamNonBlocking);
        cudaEventCreateWithFlags(&eFork, cudaEventDisableTiming);
        cudaEventCreateWithFlags(&eJ1,   cudaEventDisableTiming);
        cudaEventCreateWithFlags(&eJ2,   cudaEventDisableTiming);
        cudaEventCreateWithFlags(&eFx,   cudaEventDisableTiming);
        cudaEventCreateWithFlags(&eLoss, cudaEventDisableTiming);
    }

    // ---- fork prep across 3 streams ----
    cudaEventRecord(eFork, 0);
    cudaStreamWaitEvent(s1, eFork, 0);
    cudaStreamWaitEvent(s2, eFork, 0);

    // s0: zero aggr + gather + scalars; relation ids/mask
    k_init<<<(MM*16 + 255)/256, 256>>>(node_ids, kg_emb);
    k_relmask<<<EB, 256>>>(edge_attr);

    // s1: split weights, zero tok region, split-K token HMMA GEMM -> px[0:TT)
    k_bsplit<<<(DD*TOKN + 2*DD*DD + 255)/256, 256, 0, s1>>>(w_lin1, root1, root2);
    k_zerotok<<<(TT*16 + 255)/256, 256, 0, s1>>>();
    {
        dim3 grid(1, (TT + 127)/128, 4);
        k_mma_n64<0,0,0,1,0><<<grid, 256, 0, s1>>>(
            tokemb, (const __nv_bfloat16*)pb1h_, (const __nv_bfloat16*)pb1l_,
            b_lin1, nullptr, nullptr, px, TT, TOKN, 192);
    }

    // s2: w_lin2 split + fused u-tables
    k_wsplit<<<(TOKN*DD + 255)/256, 256, 0, s2>>>(w_lin2);
    k_ufused<<<DD, 256, 0, s2>>>(rel_emb, w_e2, b_e2, att1_w, att2_w);

    // ---- join ----
    cudaEventRecord(eJ1, s1);
    cudaEventRecord(eJ2, s2);
    cudaStreamWaitEvent(0, eJ1, 0);
    cudaStreamWaitEvent(0, eJ2, 0);

    // ---- layer 1: edge phase (unnormalized scatter), GEMM normalizes + adds + relu ----
    k_p<<<(MM + 255)/256, 256>>>(px, att1_w, att1_b);
    k_logitexp<<<(EE + 255)/256, 256>>>(px, pu1, src, dst, ps1);
    k_scatter<<<(EE*32 + 255)/256, 256>>>(px, src, dst);
    {
        dim3 grid(1, (MM + 127)/128, 1);
        k_mma_n64<1,1,1,0,1><<<grid, 256>>>(
            px, (const __nv_bfloat16*)pr1h_, (const __nv_bfloat16*)pr1l_,
            bias1, paggr, ps1, ph, MM, DD, DD);
    }

    // ---- layer 2 ----
    k_p<<<(MM + 255)/256, 256>>>(ph, att2_w, att2_b);
    k_logitexp<<<(EE + 255)/256, 256>>>(ph, pu2, src, dst, ps2);
    k_scatter<<<(EE*32 + 255)/256, 256>>>(ph, src, dst);
    {
        dim3 grid(1, (MM + 127)/128, 1);
        k_mma_n64<0,1,0,0,1><<<grid, 256>>>(
            ph, (const __nv_bfloat16*)pr2h_, (const __nv_bfloat16*)pr2l_,
            bias2, paggr, ps2, pfx, MM, DD, DD);
    }

    // ---- fork tail: losses on s1 in parallel with final GEMM ----
    cudaEventRecord(eFx, 0);
    cudaStreamWaitEvent(s1, eFx, 0);
    k_loss<<<KB + (MM + 255)/256, 256, 0, s1>>>(src, dst, rel_emb, labels, w_nt, b_nt);
    k_finalize<<<1, 1, 0, s1>>>(out, (long)out_size - 2);

    {
        dim3 grid(TOKN/64, (MM + 127)/128);
        k_gemm_mma<<<grid, 256>>>(pfx, b_lin2, out);
    }

    cudaEventRecord(eLoss, s1);
    cudaStreamWaitEvent(0, eLoss, 0);
}